// round 6
// baseline (speedup 1.0000x reference)
#include <cuda_runtime.h>
#include <cstdint>

#define N_NODES 20000
#define N_EDGES 640000
#define MUL 32
#define ATTR 8
#define RB 16
#define FH 64

#define INV_M      0.17677669529663687f
#define INV_RB     0.25f
#define INV_FH     0.125f
#define INV_SQRT3  0.5773502691896258f
#define INV_DEG    0.17677669529663687f
#define INV_2M     0.125f
#define INV_FAN    0.0625f
#define LOG2F_     0.6931471805599453f

// Scratch (device globals)
__device__ float g_s[N_NODES * MUL];
__device__ float g_v[N_NODES * MUL * 3];
__device__ float g_agg[N_NODES * MUL * 8];
// sort scratch
__device__ int g_cnt[N_NODES];
__device__ int g_pos[N_NODES];
__device__ int g_off[N_NODES + 1];
__device__ int g_perm[N_EDGES];

__device__ __forceinline__ float sspf(float x) {
    return fmaxf(x, 0.0f) + log1pf(__expf(-fabsf(x))) - LOG2F_;
}

__device__ __forceinline__ void red_add_v4(float* addr, float a, float b, float c, float d) {
    asm volatile("red.global.add.v4.f32 [%0], {%1,%2,%3,%4};"
                 :: "l"(addr), "f"(a), "f"(b), "f"(c), "f"(d) : "memory");
}

// ---- packed f32x2 helpers ----
__device__ __forceinline__ unsigned long long pack2(float x, float y) {
    unsigned long long r;
    asm("mov.b64 %0, {%1,%2};" : "=l"(r) : "f"(x), "f"(y));
    return r;
}
__device__ __forceinline__ void unpack2(float& x, float& y, unsigned long long r) {
    asm("mov.b64 {%0,%1}, %2;" : "=f"(x), "=f"(y) : "l"(r));
}
__device__ __forceinline__ void fma2(unsigned long long& d, unsigned long long a,
                                     unsigned long long b) {
    asm("fma.rn.f32x2 %0, %1, %2, %0;" : "+l"(d) : "l"(a), "l"(b));
}

// ---- bf16 pack helpers ----
// r = {upper = bf16(x1), lower = bf16(x0)}
__device__ __forceinline__ unsigned bf16x2_of(float x1, float x0) {
    unsigned r;
    asm("cvt.rn.bf16x2.f32 %0, %1, %2;" : "=r"(r) : "f"(x1), "f"(x0));
    return r;
}
// split pair (x0,x1) into hi-pack and lo-pack bf16x2 words
__device__ __forceinline__ void bf16_hilo(float x0, float x1, unsigned& hi, unsigned& lo) {
    hi = bf16x2_of(x1, x0);
    float h0 = __uint_as_float(hi << 16);
    float h1 = __uint_as_float(hi & 0xffff0000u);
    lo = bf16x2_of(x1 - h1, x0 - h0);
}

// mma.sync m16n8k16 bf16 -> f32
__device__ __forceinline__ void mma16816(float* d, const unsigned* a, const unsigned* b) {
    asm volatile(
        "mma.sync.aligned.m16n8k16.row.col.f32.bf16.bf16.f32 "
        "{%0,%1,%2,%3}, {%4,%5,%6,%7}, {%8,%9}, {%0,%1,%2,%3};"
        : "+f"(d[0]), "+f"(d[1]), "+f"(d[2]), "+f"(d[3])
        : "r"(a[0]), "r"(a[1]), "r"(a[2]), "r"(a[3]), "r"(b[0]), "r"(b[1]));
}

// ---------------------------------------------------------------------------
__global__ void k_zero() {
    int i = blockIdx.x * blockDim.x + threadIdx.x;
    float4* p = reinterpret_cast<float4*>(g_agg);
    p[i] = make_float4(0.f, 0.f, 0.f, 0.f);
    if (i < N_NODES) { g_cnt[i] = 0; g_pos[i] = 0; }
}

__global__ void k_hist(const int* __restrict__ eidx) {
    int e = blockIdx.x * blockDim.x + threadIdx.x;
    if (e < N_EDGES) atomicAdd(&g_cnt[eidx[N_EDGES + e]], 1);
}

__global__ void k_scan() {
    __shared__ int sh[1024];
    int tid = threadIdx.x;
    int base = tid * 20;
    int loc[20];
    int s = 0;
#pragma unroll
    for (int j = 0; j < 20; j++) {
        int idx = base + j;
        int c = (idx < N_NODES) ? g_cnt[idx] : 0;
        loc[j] = s;
        s += c;
    }
    sh[tid] = s;
    __syncthreads();
    for (int off = 1; off < 1024; off <<= 1) {
        int v = (tid >= off) ? sh[tid - off] : 0;
        __syncthreads();
        sh[tid] += v;
        __syncthreads();
    }
    int pre = (tid == 0) ? 0 : sh[tid - 1];
#pragma unroll
    for (int j = 0; j < 20; j++) {
        int idx = base + j;
        if (idx < N_NODES) g_off[idx] = pre + loc[j];
    }
    if (tid == 1023) g_off[N_NODES] = sh[1023];
}

__global__ void k_scatter(const int* __restrict__ eidx) {
    int e = blockIdx.x * blockDim.x + threadIdx.x;
    if (e < N_EDGES) {
        int dst = eidx[N_EDGES + e];
        int r = atomicAdd(&g_pos[dst], 1);
        g_perm[g_off[dst] + r] = e;
    }
}

// ---------------------------------------------------------------------------
// Kernel 1: linear_1
// ---------------------------------------------------------------------------
__global__ void k_lin1(const float* __restrict__ node_s,
                       const float* __restrict__ node_v,
                       const float* __restrict__ W1s,
                       const float* __restrict__ W1v) {
    __shared__ float sW1s[1024];
    __shared__ float sW1v[1024];
    int tid = threadIdx.x;
    for (int i = tid; i < 1024; i += 256) {
        sW1s[i] = W1s[i] * INV_M;
        sW1v[i] = W1v[i] * INV_M;
    }
    __syncthreads();

    int gt = blockIdx.x * 256 + tid;
    int node = gt >> 1;
    int h = gt & 1;
    if (node >= N_NODES) return;

    float accs[16];
    float accv[16][3];
#pragma unroll
    for (int w = 0; w < 16; w++) { accs[w] = 0.f; accv[w][0] = accv[w][1] = accv[w][2] = 0.f; }

    const float* srow = node_s + node * 32;
    const float* vrow = node_v + node * 96;
    for (int u = 0; u < 32; u++) {
        float su = srow[u];
        float vx = vrow[u * 3 + 0], vy = vrow[u * 3 + 1], vz = vrow[u * 3 + 2];
        const float* ws = &sW1s[u * 32 + h * 16];
        const float* wv = &sW1v[u * 32 + h * 16];
#pragma unroll
        for (int w = 0; w < 16; w++) {
            accs[w]    += su * ws[w];
            accv[w][0] += vx * wv[w];
            accv[w][1] += vy * wv[w];
            accv[w][2] += vz * wv[w];
        }
    }
    float* so = g_s + node * 32 + h * 16;
    float* vo = g_v + node * 96 + h * 48;
#pragma unroll
    for (int w = 0; w < 16; w++) {
        so[w] = accs[w];
        vo[w * 3 + 0] = accv[w][0];
        vo[w * 3 + 1] = accv[w][1];
        vo[w * 3 + 2] = accv[w][2];
    }
}

// ---------------------------------------------------------------------------
// Kernel 2: edge kernel. GEMM1 scalar fp32; GEMM2 via mma.sync bf16 hi/lo
// 3-term split (tensor pipe); warp-cooperative TP + run-accumulated scatter.
//
// Smem units (f32/u32):
//   [0:4224)       phA_hi  [128 edges][33 kk]  (bf16x2 pairs along k)
//   [4224:8448)    phA_lo
//   [8448:12672)   pB_hi   [128 n][33 kk]
//   [12672:16896)  pB_lo
//   [0:16384)      sw[128][128] f32 (overlay after MMA, xor-swizzled)
//   [16896:17920)  Wr1 scaled
//   [17920:20096)  emb [128][17]
//   [20096:20992)  meta: sperm/ssrc/sdst/sy0 (128 ea), sy1[384]
// ---------------------------------------------------------------------------
#define ET 128
#define PHA_HI 0
#define PHA_LO 4224
#define PB_HI  8448
#define PB_LO  12672
#define WR1_OFF 16896
#define EMB_OFF 17920
#define META_OFF 20096
#define EDGE_SMEM_FLOATS 20992

__global__ void __launch_bounds__(256, 2)
k_edge(const float* __restrict__ emb,
       const float* __restrict__ y0,
       const float* __restrict__ y1,
       const int*   __restrict__ eidx,
       const float* __restrict__ Wr1,
       const float* __restrict__ Wr2) {
    extern __shared__ float sm[];
    unsigned* su   = reinterpret_cast<unsigned*>(sm);
    float* sw   = sm;                     // overlay after MMA
    float* sWr1 = sm + WR1_OFF;
    float* semb = sm + EMB_OFF;
    int*   sperm = (int*)(sm + META_OFF);
    int*   ssrc  = sperm + 128;
    int*   sdst  = ssrc + 128;
    float* sy0   = (float*)(sdst + 128);
    float* sy1   = sy0 + 128;

    int tid = threadIdx.x;
    int p0 = blockIdx.x * ET;

    if (tid < 128) sperm[tid] = g_perm[p0 + tid];
    for (int i = tid; i < 1024; i += 256) sWr1[i] = Wr1[i] * INV_RB;
    // pack B = Wr2^T into bf16x2 hi/lo: pB[n][kk] = {k=2kk+1 | k=2kk}
    for (int i = tid; i < 4096; i += 256) {
        int n = i & 127, kk = i >> 7;
        float sc = INV_FH * INV_DEG * ((n >= 96) ? INV_SQRT3 : 1.0f);
        float w0 = Wr2[(2 * kk) * 128 + n] * sc;
        float w1 = Wr2[(2 * kk + 1) * 128 + n] * sc;
        unsigned hi, lo;
        bf16_hilo(w0, w1, hi, lo);
        su[PB_HI + n * 33 + kk] = hi;
        su[PB_LO + n * 33 + kk] = lo;
    }
    __syncthreads();

    if (tid < 128) {
        int e = sperm[tid];
        ssrc[tid] = eidx[e];
        sdst[tid] = eidx[N_EDGES + e];
        sy0[tid] = y0[e];
    }
    for (int i = tid; i < 384; i += 256) {
        int pos = i / 3, comp = i - pos * 3;
        sy1[i] = y1[sperm[pos] * 3 + comp];
    }
    for (int i = tid; i < ET * RB; i += 256) {
        int pos = i >> 4, k = i & 15;
        semb[pos * 17 + k] = emb[sperm[pos] * 16 + k];
    }
    __syncthreads();

    int lane = tid & 31;
    int th = tid >> 5;     // warp id 0..7

    // ---- GEMM1 (fp32): edges lane+32j (j=0..3), hidden cols th*8..+7 ----
    float acc1[4][8];
#pragma unroll
    for (int j = 0; j < 4; j++)
#pragma unroll
        for (int m = 0; m < 8; m++) acc1[j][m] = 0.f;

    for (int k = 0; k < 16; k++) {
        float em[4];
#pragma unroll
        for (int j = 0; j < 4; j++) em[j] = semb[(lane + 32 * j) * 17 + k];
        float wr[8];
#pragma unroll
        for (int m = 0; m < 8; m++) wr[m] = sWr1[k * 64 + th * 8 + m];
#pragma unroll
        for (int j = 0; j < 4; j++)
#pragma unroll
            for (int m = 0; m < 8; m++) acc1[j][m] += em[j] * wr[m];
    }
    // softplus + bf16 hi/lo pack -> phA[edge][kk], kk = th*4 + m/2
#pragma unroll
    for (int j = 0; j < 4; j++) {
        int edge = lane + 32 * j;
#pragma unroll
        for (int m = 0; m < 8; m += 2) {
            float x0 = sspf(acc1[j][m]);
            float x1 = sspf(acc1[j][m + 1]);
            unsigned hi, lo;
            bf16_hilo(x0, x1, hi, lo);
            int kk = th * 4 + (m >> 1);
            su[PHA_HI + edge * 33 + kk] = hi;
            su[PHA_LO + edge * 33 + kk] = lo;
        }
    }
    __syncthreads();

    // ---- GEMM2 via mma.sync: warp th owns edges [th*16, th*16+16) ----
    int g = lane >> 2;       // 0..7
    int t = lane & 3;        // 0..3
    float d[16][4];
#pragma unroll
    for (int nt = 0; nt < 16; nt++)
#pragma unroll
        for (int c = 0; c < 4; c++) d[nt][c] = 0.f;

    {
        int r0 = th * 16 + g;       // A rows
        int r1 = r0 + 8;
#pragma unroll
        for (int ks = 0; ks < 4; ks++) {
            int kk0 = ks * 8 + t;
            unsigned ahi[4], alo[4];
            ahi[0] = su[PHA_HI + r0 * 33 + kk0];
            ahi[1] = su[PHA_HI + r1 * 33 + kk0];
            ahi[2] = su[PHA_HI + r0 * 33 + kk0 + 4];
            ahi[3] = su[PHA_HI + r1 * 33 + kk0 + 4];
            alo[0] = su[PHA_LO + r0 * 33 + kk0];
            alo[1] = su[PHA_LO + r1 * 33 + kk0];
            alo[2] = su[PHA_LO + r0 * 33 + kk0 + 4];
            alo[3] = su[PHA_LO + r1 * 33 + kk0 + 4];
#pragma unroll
            for (int nt = 0; nt < 16; nt++) {
                int n = nt * 8 + g;
                unsigned bhi[2], blo[2];
                bhi[0] = su[PB_HI + n * 33 + kk0];
                bhi[1] = su[PB_HI + n * 33 + kk0 + 4];
                blo[0] = su[PB_LO + n * 33 + kk0];
                blo[1] = su[PB_LO + n * 33 + kk0 + 4];
                mma16816(d[nt], ahi, bhi);
                mma16816(d[nt], alo, bhi);
                mma16816(d[nt], ahi, blo);
            }
        }
    }
    __syncthreads();   // phA/pB dead; safe to overlay sw

    // ---- store D -> sw[edge][col] with xor swizzle (bits 2-4 by edge&7) ----
    {
        int e0 = th * 16 + g;
        int e1 = e0 + 8;
        int sw0 = (e0 & 7) << 2;
        int sw1 = (e1 & 7) << 2;
#pragma unroll
        for (int nt = 0; nt < 16; nt++) {
            int c = nt * 8 + 2 * t;
            int b = c & ~31;
            int cc = c & 31;
            *(float2*)&sw[e0 * 128 + b + (cc ^ sw0)] = make_float2(d[nt][0], d[nt][1]);
            *(float2*)&sw[e1 * 128 + b + (cc ^ sw1)] = make_float2(d[nt][2], d[nt][3]);
        }
    }
    __syncthreads();

    // ---- warp-cooperative TP: warp th owns edges [th*16, th*16+16), lane = u ----
    float A[8];
#pragma unroll
    for (int q = 0; q < 8; q++) A[q] = 0.f;

    int base = th * 16;
    int cur = sdst[base];
#pragma unroll 4
    for (int j = 0; j < 16; j++) {
        int pos = base + j;
        int dd = sdst[pos];
        if (dd != cur) {
            float* q = g_agg + (size_t)cur * 256 + lane * 8;
            red_add_v4(q,     A[0], A[1], A[2], A[3]);
            red_add_v4(q + 4, A[4], A[5], A[6], A[7]);
#pragma unroll
            for (int qq = 0; qq < 8; qq++) A[qq] = 0.f;
            cur = dd;
        }
        int src = ssrc[pos];
        float yy0 = sy0[pos];
        float y1x = sy1[pos * 3 + 0], y1y = sy1[pos * 3 + 1], y1z = sy1[pos * 3 + 2];
        float se = g_s[src * 32 + lane];
        const float* vp = g_v + src * 96 + lane * 3;
        float vx = vp[0], vy = vp[1], vz = vp[2];
        int sx = lane ^ ((pos & 7) << 2);
        int wb = pos * 128;
        float w1 = sw[wb + sx], w2 = sw[wb + 32 + sx], w3 = sw[wb + 64 + sx], w4 = sw[wb + 96 + sx];

        A[0] += w1 * (se * yy0);
        A[1] += w4 * (vx * y1x + vy * y1y + vz * y1z);
        float a = w2 * se;
        A[2] += a * y1x; A[3] += a * y1y; A[4] += a * y1z;
        float b = w3 * yy0;
        A[5] += b * vx;  A[6] += b * vy;  A[7] += b * vz;
    }
    float* q = g_agg + (size_t)cur * 256 + lane * 8;
    red_add_v4(q,     A[0], A[1], A[2], A[3]);
    red_add_v4(q + 4, A[4], A[5], A[6], A[7]);
}

// ---------------------------------------------------------------------------
// Kernel 3: linear_2 + self-connection
// ---------------------------------------------------------------------------
#define OUT_SMEM_FLOATS (2048 + 2048 + 8192 + 8192)

__global__ void __launch_bounds__(256)
k_out(const float* __restrict__ node_s,
      const float* __restrict__ node_v,
      const float* __restrict__ attrs,
      const float* __restrict__ W2s,
      const float* __restrict__ W2v,
      const float* __restrict__ Wscs,
      const float* __restrict__ Wscv,
      float* __restrict__ out) {
    extern __shared__ float sm[];
    float* sW2s  = sm;
    float* sW2v  = sW2s + 2048;
    float* sWscs = sW2v + 2048;
    float* sWscv = sWscs + 8192;

    int tid = threadIdx.x;
    for (int i = tid; i < 2048; i += 256) { sW2s[i]  = W2s[i]  * INV_2M;  sW2v[i]  = W2v[i]  * INV_2M; }
    for (int i = tid; i < 8192; i += 256) { sWscs[i] = Wscs[i] * INV_FAN; sWscv[i] = Wscv[i] * INV_FAN; }
    __syncthreads();

    int node = blockIdx.x * 32 + (tid >> 3);
    int part = tid & 7;
    int wo = part * 4;

    unsigned long long accs2[2] = {0ull, 0ull};
    unsigned long long accv2[3][2] = {{0ull, 0ull}, {0ull, 0ull}, {0ull, 0ull}};

    const float4* ag = reinterpret_cast<const float4*>(g_agg + (size_t)node * 256);
#pragma unroll 4
    for (int u = 0; u < 32; u++) {
        float4 Aq = ag[u * 2 + 0];
        float4 Bq = ag[u * 2 + 1];
#pragma unroll
        for (int half = 0; half < 2; half++) {
            int k = half * 32 + u;
            ulonglong2 ws = *(const ulonglong2*)&sW2s[k * 32 + wo];
            ulonglong2 wv = *(const ulonglong2*)&sW2v[k * 32 + wo];
            float as  = half ? Aq.y : Aq.x;
            float avx = half ? Bq.y : Aq.z;
            float avy = half ? Bq.z : Aq.w;
            float avz = half ? Bq.w : Bq.x;
            unsigned long long as2  = pack2(as, as);
            unsigned long long avx2 = pack2(avx, avx);
            unsigned long long avy2 = pack2(avy, avy);
            unsigned long long avz2 = pack2(avz, avz);
            fma2(accs2[0], as2, ws.x);
            fma2(accs2[1], as2, ws.y);
            fma2(accv2[0][0], avx2, wv.x);
            fma2(accv2[0][1], avx2, wv.y);
            fma2(accv2[1][0], avy2, wv.x);
            fma2(accv2[1][1], avy2, wv.y);
            fma2(accv2[2][0], avz2, wv.x);
            fma2(accv2[2][1], avz2, wv.y);
        }
    }

    unsigned long long at2[8];
    const float* arow = attrs + node * 8;
#pragma unroll
    for (int v = 0; v < 8; v++) { float a = arow[v]; at2[v] = pack2(a, a); }

    const float* srow = node_s + node * 32;
    const float* vrow = node_v + node * 96;
#pragma unroll 2
    for (int u = 0; u < 32; u++) {
        float su = srow[u];
        float vx = vrow[u * 3 + 0], vy = vrow[u * 3 + 1], vz = vrow[u * 3 + 2];
        unsigned long long Ts[2] = {0ull, 0ull};
        unsigned long long Tv[2] = {0ull, 0ull};
#pragma unroll
        for (int v = 0; v < 8; v++) {
            ulonglong2 ps = *(const ulonglong2*)&sWscs[(u * 8 + v) * 32 + wo];
            ulonglong2 pv = *(const ulonglong2*)&sWscv[(u * 8 + v) * 32 + wo];
            fma2(Ts[0], at2[v], ps.x);
            fma2(Ts[1], at2[v], ps.y);
            fma2(Tv[0], at2[v], pv.x);
            fma2(Tv[1], at2[v], pv.y);
        }
        unsigned long long su2 = pack2(su, su);
        unsigned long long vx2 = pack2(vx, vx);
        unsigned long long vy2 = pack2(vy, vy);
        unsigned long long vz2 = pack2(vz, vz);
#pragma unroll
        for (int p = 0; p < 2; p++) {
            fma2(accs2[p], su2, Ts[p]);
            fma2(accv2[0][p], vx2, Tv[p]);
            fma2(accv2[1][p], vy2, Tv[p]);
            fma2(accv2[2][p], vz2, Tv[p]);
        }
    }

    float* o = out + (size_t)node * 128;
#pragma unroll
    for (int p = 0; p < 2; p++) {
        float s0, s1;
        unpack2(s0, s1, accs2[p]);
        float v0[3], v1[3];
        unpack2(v0[0], v1[0], accv2[0][p]);
        unpack2(v0[1], v1[1], accv2[1][p]);
        unpack2(v0[2], v1[2], accv2[2][p]);
        int w0 = wo + p * 2;
        o[w0]     = s0;
        o[w0 + 1] = s1;
        o[32 + w0 * 3 + 0] = v0[0];
        o[32 + w0 * 3 + 1] = v0[1];
        o[32 + w0 * 3 + 2] = v0[2];
        o[32 + (w0 + 1) * 3 + 0] = v1[0];
        o[32 + (w0 + 1) * 3 + 1] = v1[1];
        o[32 + (w0 + 1) * 3 + 2] = v1[2];
    }
}

// ---------------------------------------------------------------------------
extern "C" void kernel_launch(void* const* d_in, const int* in_sizes, int n_in,
                              void* d_out, int out_size) {
    const float* node_s     = (const float*)d_in[0];
    const float* node_v     = (const float*)d_in[1];
    const float* node_attrs = (const float*)d_in[2];
    const float* edge_emb   = (const float*)d_in[3];
    const float* edge_y0    = (const float*)d_in[4];
    const float* edge_y1    = (const float*)d_in[5];
    const int*   edge_index = (const int*)d_in[6];
    const float* W1s        = (const float*)d_in[7];
    const float* W1v        = (const float*)d_in[8];
    const float* Wr1        = (const float*)d_in[9];
    const float* Wr2        = (const float*)d_in[10];
    const float* W2s        = (const float*)d_in[11];
    const float* W2v        = (const float*)d_in[12];
    const float* Wscs       = (const float*)d_in[13];
    const float* Wscv       = (const float*)d_in[14];
    float* out = (float*)d_out;

    cudaFuncSetAttribute(k_edge, cudaFuncAttributeMaxDynamicSharedMemorySize,
                         EDGE_SMEM_FLOATS * sizeof(float));
    cudaFuncSetAttribute(k_out, cudaFuncAttributeMaxDynamicSharedMemorySize,
                         OUT_SMEM_FLOATS * sizeof(float));

    k_zero<<<5000, 256>>>();
    k_hist<<<2500, 256>>>(edge_index);
    k_scan<<<1, 1024>>>();
    k_scatter<<<2500, 256>>>(edge_index);
    k_lin1<<<(2 * N_NODES + 255) / 256, 256>>>(node_s, node_v, W1s, W1v);
    k_edge<<<N_EDGES / ET, 256, EDGE_SMEM_FLOATS * sizeof(float)>>>(
        edge_emb, edge_y0, edge_y1, edge_index, Wr1, Wr2);
    k_out<<<(N_NODES * 8) / 256, 256, OUT_SMEM_FLOATS * sizeof(float)>>>(
        node_s, node_v, node_attrs, W2s, W2v, Wscs, Wscv, out);
}

// round 7
// speedup vs baseline: 1.0561x; 1.0561x over previous
#include <cuda_runtime.h>
#include <cstdint>

#define N_NODES 20000
#define N_EDGES 640000
#define MUL 32
#define ATTR 8
#define RB 16
#define FH 64

#define INV_M      0.17677669529663687f
#define INV_RB     0.25f
#define INV_FH     0.125f
#define INV_SQRT3  0.5773502691896258f
#define INV_DEG    0.17677669529663687f
#define INV_2M     0.125f
#define INV_FAN    0.0625f
#define LOG2F_     0.6931471805599453f

// Scratch (device globals)
__device__ float g_s[N_NODES * MUL];
__device__ float g_v[N_NODES * MUL * 3];      // SoA: [node][comp(3)][u(32)]
__device__ float g_agg[N_NODES * MUL * 8];
// sort scratch
__device__ int g_cnt[N_NODES];
__device__ int g_pos[N_NODES];
__device__ int g_off[N_NODES + 1];
__device__ int g_perm[N_EDGES];

__device__ __forceinline__ float sspf(float x) {
    return fmaxf(x, 0.0f) + log1pf(__expf(-fabsf(x))) - LOG2F_;
}

// NOTE: no "memory" clobber — g_agg is write-only in k_edge and atomic adds
// commute, so the compiler may reorder independent loads across these.
__device__ __forceinline__ void red_add_v4(float* addr, float a, float b, float c, float d) {
    asm volatile("red.global.add.v4.f32 [%0], {%1,%2,%3,%4};"
                 :: "l"(addr), "f"(a), "f"(b), "f"(c), "f"(d));
}

// ---- packed f32x2 helpers ----
__device__ __forceinline__ unsigned long long pack2(float x, float y) {
    unsigned long long r;
    asm("mov.b64 %0, {%1,%2};" : "=l"(r) : "f"(x), "f"(y));
    return r;
}
__device__ __forceinline__ void unpack2(float& x, float& y, unsigned long long r) {
    asm("mov.b64 {%0,%1}, %2;" : "=f"(x), "=f"(y) : "l"(r));
}
__device__ __forceinline__ void fma2(unsigned long long& d, unsigned long long a,
                                     unsigned long long b) {
    asm("fma.rn.f32x2 %0, %1, %2, %0;" : "+l"(d) : "l"(a), "l"(b));
}

// ---- bf16 pack helpers ----
__device__ __forceinline__ unsigned bf16x2_of(float x1, float x0) {
    unsigned r;
    asm("cvt.rn.bf16x2.f32 %0, %1, %2;" : "=r"(r) : "f"(x1), "f"(x0));
    return r;
}
__device__ __forceinline__ void bf16_hilo(float x0, float x1, unsigned& hi, unsigned& lo) {
    hi = bf16x2_of(x1, x0);
    float h0 = __uint_as_float(hi << 16);
    float h1 = __uint_as_float(hi & 0xffff0000u);
    lo = bf16x2_of(x1 - h1, x0 - h0);
}

__device__ __forceinline__ void mma16816(float* d, const unsigned* a, const unsigned* b) {
    asm volatile(
        "mma.sync.aligned.m16n8k16.row.col.f32.bf16.bf16.f32 "
        "{%0,%1,%2,%3}, {%4,%5,%6,%7}, {%8,%9}, {%0,%1,%2,%3};"
        : "+f"(d[0]), "+f"(d[1]), "+f"(d[2]), "+f"(d[3])
        : "r"(a[0]), "r"(a[1]), "r"(a[2]), "r"(a[3]), "r"(b[0]), "r"(b[1]));
}

// ---------------------------------------------------------------------------
__global__ void k_zero() {
    int i = blockIdx.x * blockDim.x + threadIdx.x;
    float4* p = reinterpret_cast<float4*>(g_agg);
    p[i] = make_float4(0.f, 0.f, 0.f, 0.f);
    if (i < N_NODES) { g_cnt[i] = 0; g_pos[i] = 0; }
}

__global__ void k_hist(const int* __restrict__ eidx) {
    int e = blockIdx.x * blockDim.x + threadIdx.x;
    if (e < N_EDGES) atomicAdd(&g_cnt[eidx[N_EDGES + e]], 1);
}

__global__ void k_scan() {
    __shared__ int sh[1024];
    int tid = threadIdx.x;
    int base = tid * 20;
    int loc[20];
    int s = 0;
#pragma unroll
    for (int j = 0; j < 20; j++) {
        int idx = base + j;
        int c = (idx < N_NODES) ? g_cnt[idx] : 0;
        loc[j] = s;
        s += c;
    }
    sh[tid] = s;
    __syncthreads();
    for (int off = 1; off < 1024; off <<= 1) {
        int v = (tid >= off) ? sh[tid - off] : 0;
        __syncthreads();
        sh[tid] += v;
        __syncthreads();
    }
    int pre = (tid == 0) ? 0 : sh[tid - 1];
#pragma unroll
    for (int j = 0; j < 20; j++) {
        int idx = base + j;
        if (idx < N_NODES) g_off[idx] = pre + loc[j];
    }
    if (tid == 1023) g_off[N_NODES] = sh[1023];
}

__global__ void k_scatter(const int* __restrict__ eidx) {
    int e = blockIdx.x * blockDim.x + threadIdx.x;
    if (e < N_EDGES) {
        int dst = eidx[N_EDGES + e];
        int r = atomicAdd(&g_pos[dst], 1);
        g_perm[g_off[dst] + r] = e;
    }
}

// ---------------------------------------------------------------------------
// Kernel 1: linear_1 (writes g_v in SoA [node][comp][32])
// ---------------------------------------------------------------------------
__global__ void k_lin1(const float* __restrict__ node_s,
                       const float* __restrict__ node_v,
                       const float* __restrict__ W1s,
                       const float* __restrict__ W1v) {
    __shared__ float sW1s[1024];
    __shared__ float sW1v[1024];
    int tid = threadIdx.x;
    for (int i = tid; i < 1024; i += 256) {
        sW1s[i] = W1s[i] * INV_M;
        sW1v[i] = W1v[i] * INV_M;
    }
    __syncthreads();

    int gt = blockIdx.x * 256 + tid;
    int node = gt >> 1;
    int h = gt & 1;
    if (node >= N_NODES) return;

    float accs[16];
    float accv[16][3];
#pragma unroll
    for (int w = 0; w < 16; w++) { accs[w] = 0.f; accv[w][0] = accv[w][1] = accv[w][2] = 0.f; }

    const float* srow = node_s + node * 32;
    const float* vrow = node_v + node * 96;
    for (int u = 0; u < 32; u++) {
        float su = srow[u];
        float vx = vrow[u * 3 + 0], vy = vrow[u * 3 + 1], vz = vrow[u * 3 + 2];
        const float* ws = &sW1s[u * 32 + h * 16];
        const float* wv = &sW1v[u * 32 + h * 16];
#pragma unroll
        for (int w = 0; w < 16; w++) {
            accs[w]    += su * ws[w];
            accv[w][0] += vx * wv[w];
            accv[w][1] += vy * wv[w];
            accv[w][2] += vz * wv[w];
        }
    }
    float* so = g_s + node * 32 + h * 16;
    float* vo = g_v + node * 96 + h * 16;     // SoA: + comp*32
#pragma unroll
    for (int w = 0; w < 16; w++) {
        so[w] = accs[w];
        vo[w]      = accv[w][0];
        vo[32 + w] = accv[w][1];
        vo[64 + w] = accv[w][2];
    }
}

// ---------------------------------------------------------------------------
// Kernel 2: edge kernel. GEMM1 scalar fp32; GEMM2 via mma.sync bf16 hi/lo
// 3-term split; warp-cooperative TP with pipelined coalesced gathers.
// ---------------------------------------------------------------------------
#define ET 128
#define PHA_HI 0
#define PHA_LO 4224
#define PB_HI  8448
#define PB_LO  12672
#define WR1_OFF 16896
#define EMB_OFF 17920
#define META_OFF 20096
#define EDGE_SMEM_FLOATS 20992

__global__ void __launch_bounds__(256, 2)
k_edge(const float* __restrict__ emb,
       const float* __restrict__ y0,
       const float* __restrict__ y1,
       const int*   __restrict__ eidx,
       const float* __restrict__ Wr1,
       const float* __restrict__ Wr2) {
    extern __shared__ float sm[];
    unsigned* su   = reinterpret_cast<unsigned*>(sm);
    float* sw   = sm;                     // overlay after MMA
    float* sWr1 = sm + WR1_OFF;
    float* semb = sm + EMB_OFF;
    int*   sperm = (int*)(sm + META_OFF);
    int*   ssrc  = sperm + 128;
    int*   sdst  = ssrc + 128;
    float* sy0   = (float*)(sdst + 128);
    float* sy1   = sy0 + 128;

    int tid = threadIdx.x;
    int p0 = blockIdx.x * ET;

    if (tid < 128) sperm[tid] = g_perm[p0 + tid];
    for (int i = tid; i < 1024; i += 256) sWr1[i] = Wr1[i] * INV_RB;
    for (int i = tid; i < 4096; i += 256) {
        int n = i & 127, kk = i >> 7;
        float sc = INV_FH * INV_DEG * ((n >= 96) ? INV_SQRT3 : 1.0f);
        float w0 = Wr2[(2 * kk) * 128 + n] * sc;
        float w1 = Wr2[(2 * kk + 1) * 128 + n] * sc;
        unsigned hi, lo;
        bf16_hilo(w0, w1, hi, lo);
        su[PB_HI + n * 33 + kk] = hi;
        su[PB_LO + n * 33 + kk] = lo;
    }
    __syncthreads();

    if (tid < 128) {
        int e = sperm[tid];
        ssrc[tid] = eidx[e];
        sdst[tid] = eidx[N_EDGES + e];
        sy0[tid] = y0[e];
    }
    for (int i = tid; i < 384; i += 256) {
        int pos = i / 3, comp = i - pos * 3;
        sy1[i] = y1[sperm[pos] * 3 + comp];
    }
    for (int i = tid; i < ET * RB; i += 256) {
        int pos = i >> 4, k = i & 15;
        semb[pos * 17 + k] = emb[sperm[pos] * 16 + k];
    }
    __syncthreads();

    int lane = tid & 31;
    int th = tid >> 5;

    // ---- GEMM1 (fp32): edges lane+32j, hidden cols th*8..+7 ----
    float acc1[4][8];
#pragma unroll
    for (int j = 0; j < 4; j++)
#pragma unroll
        for (int m = 0; m < 8; m++) acc1[j][m] = 0.f;

    for (int k = 0; k < 16; k++) {
        float em[4];
#pragma unroll
        for (int j = 0; j < 4; j++) em[j] = semb[(lane + 32 * j) * 17 + k];
        float wr[8];
#pragma unroll
        for (int m = 0; m < 8; m++) wr[m] = sWr1[k * 64 + th * 8 + m];
#pragma unroll
        for (int j = 0; j < 4; j++)
#pragma unroll
            for (int m = 0; m < 8; m++) acc1[j][m] += em[j] * wr[m];
    }
#pragma unroll
    for (int j = 0; j < 4; j++) {
        int edge = lane + 32 * j;
#pragma unroll
        for (int m = 0; m < 8; m += 2) {
            float x0 = sspf(acc1[j][m]);
            float x1 = sspf(acc1[j][m + 1]);
            unsigned hi, lo;
            bf16_hilo(x0, x1, hi, lo);
            int kk = th * 4 + (m >> 1);
            su[PHA_HI + edge * 33 + kk] = hi;
            su[PHA_LO + edge * 33 + kk] = lo;
        }
    }
    __syncthreads();

    // ---- GEMM2 via mma.sync: warp th owns edges [th*16, th*16+16) ----
    int g = lane >> 2;
    int t = lane & 3;
    float d[16][4];
#pragma unroll
    for (int nt = 0; nt < 16; nt++)
#pragma unroll
        for (int c = 0; c < 4; c++) d[nt][c] = 0.f;

    {
        int r0 = th * 16 + g;
        int r1 = r0 + 8;
#pragma unroll
        for (int ks = 0; ks < 4; ks++) {
            int kk0 = ks * 8 + t;
            unsigned ahi[4], alo[4];
            ahi[0] = su[PHA_HI + r0 * 33 + kk0];
            ahi[1] = su[PHA_HI + r1 * 33 + kk0];
            ahi[2] = su[PHA_HI + r0 * 33 + kk0 + 4];
            ahi[3] = su[PHA_HI + r1 * 33 + kk0 + 4];
            alo[0] = su[PHA_LO + r0 * 33 + kk0];
            alo[1] = su[PHA_LO + r1 * 33 + kk0];
            alo[2] = su[PHA_LO + r0 * 33 + kk0 + 4];
            alo[3] = su[PHA_LO + r1 * 33 + kk0 + 4];
#pragma unroll
            for (int nt = 0; nt < 16; nt++) {
                int n = nt * 8 + g;
                unsigned bhi[2], blo[2];
                bhi[0] = su[PB_HI + n * 33 + kk0];
                bhi[1] = su[PB_HI + n * 33 + kk0 + 4];
                blo[0] = su[PB_LO + n * 33 + kk0];
                blo[1] = su[PB_LO + n * 33 + kk0 + 4];
                mma16816(d[nt], ahi, bhi);
                mma16816(d[nt], alo, bhi);
                mma16816(d[nt], ahi, blo);
            }
        }
    }
    __syncthreads();   // phA/pB dead; safe to overlay sw

    // ---- store D -> sw[edge][col] with xor swizzle ----
    {
        int e0 = th * 16 + g;
        int e1 = e0 + 8;
        int sw0 = (e0 & 7) << 2;
        int sw1 = (e1 & 7) << 2;
#pragma unroll
        for (int nt = 0; nt < 16; nt++) {
            int c = nt * 8 + 2 * t;
            int b = c & ~31;
            int cc = c & 31;
            *(float2*)&sw[e0 * 128 + b + (cc ^ sw0)] = make_float2(d[nt][0], d[nt][1]);
            *(float2*)&sw[e1 * 128 + b + (cc ^ sw1)] = make_float2(d[nt][2], d[nt][3]);
        }
    }
    // warp th reads ONLY sw rows [th*16, th*16+16) which it wrote itself:
    __syncwarp();

    // ---- warp-cooperative TP with pipelined coalesced gathers, lane = u ----
    int base = th * 16;

    // preload all 16 scalar features (independent, MLP=16)
    float se_r[16];
#pragma unroll
    for (int j = 0; j < 16; j++) se_r[j] = g_s[ssrc[base + j] * 32 + lane];

    // depth-1 pipeline on vector features (SoA: one 128B line per comp)
    const float* vp0 = g_v + ssrc[base] * 96 + lane;
    float vxc = vp0[0], vyc = vp0[32], vzc = vp0[64];

    float A[8];
#pragma unroll
    for (int q = 0; q < 8; q++) A[q] = 0.f;

    int cur = sdst[base];
#pragma unroll
    for (int j = 0; j < 16; j++) {
        int pos = base + j;
        float vxn = 0.f, vyn = 0.f, vzn = 0.f;
        if (j < 15) {
            const float* vpn = g_v + ssrc[pos + 1] * 96 + lane;
            vxn = vpn[0]; vyn = vpn[32]; vzn = vpn[64];
        }
        int dd = sdst[pos];
        if (dd != cur) {
            float* q = g_agg + (size_t)cur * 256 + lane * 8;
            red_add_v4(q,     A[0], A[1], A[2], A[3]);
            red_add_v4(q + 4, A[4], A[5], A[6], A[7]);
#pragma unroll
            for (int qq = 0; qq < 8; qq++) A[qq] = 0.f;
            cur = dd;
        }
        float yy0 = sy0[pos];
        float y1x = sy1[pos * 3 + 0], y1y = sy1[pos * 3 + 1], y1z = sy1[pos * 3 + 2];
        float se = se_r[j];
        int sx = lane ^ ((pos & 7) << 2);
        int wb = pos * 128;
        float w1 = sw[wb + sx], w2 = sw[wb + 32 + sx], w3 = sw[wb + 64 + sx], w4 = sw[wb + 96 + sx];

        A[0] += w1 * (se * yy0);
        A[1] += w4 * (vxc * y1x + vyc * y1y + vzc * y1z);
        float a = w2 * se;
        A[2] += a * y1x; A[3] += a * y1y; A[4] += a * y1z;
        float b = w3 * yy0;
        A[5] += b * vxc; A[6] += b * vyc; A[7] += b * vzc;

        vxc = vxn; vyc = vyn; vzc = vzn;
    }
    float* q = g_agg + (size_t)cur * 256 + lane * 8;
    red_add_v4(q,     A[0], A[1], A[2], A[3]);
    red_add_v4(q + 4, A[4], A[5], A[6], A[7]);
}

// ---------------------------------------------------------------------------
// Kernel 3: linear_2 + self-connection
// ---------------------------------------------------------------------------
#define OUT_SMEM_FLOATS (2048 + 2048 + 8192 + 8192)

__global__ void __launch_bounds__(256)
k_out(const float* __restrict__ node_s,
      const float* __restrict__ node_v,
      const float* __restrict__ attrs,
      const float* __restrict__ W2s,
      const float* __restrict__ W2v,
      const float* __restrict__ Wscs,
      const float* __restrict__ Wscv,
      float* __restrict__ out) {
    extern __shared__ float sm[];
    float* sW2s  = sm;
    float* sW2v  = sW2s + 2048;
    float* sWscs = sW2v + 2048;
    float* sWscv = sWscs + 8192;

    int tid = threadIdx.x;
    for (int i = tid; i < 2048; i += 256) { sW2s[i]  = W2s[i]  * INV_2M;  sW2v[i]  = W2v[i]  * INV_2M; }
    for (int i = tid; i < 8192; i += 256) { sWscs[i] = Wscs[i] * INV_FAN; sWscv[i] = Wscv[i] * INV_FAN; }
    __syncthreads();

    int node = blockIdx.x * 32 + (tid >> 3);
    int part = tid & 7;
    int wo = part * 4;

    unsigned long long accs2[2] = {0ull, 0ull};
    unsigned long long accv2[3][2] = {{0ull, 0ull}, {0ull, 0ull}, {0ull, 0ull}};

    const float4* ag = reinterpret_cast<const float4*>(g_agg + (size_t)node * 256);
#pragma unroll 4
    for (int u = 0; u < 32; u++) {
        float4 Aq = ag[u * 2 + 0];
        float4 Bq = ag[u * 2 + 1];
#pragma unroll
        for (int half = 0; half < 2; half++) {
            int k = half * 32 + u;
            ulonglong2 ws = *(const ulonglong2*)&sW2s[k * 32 + wo];
            ulonglong2 wv = *(const ulonglong2*)&sW2v[k * 32 + wo];
            float as  = half ? Aq.y : Aq.x;
            float avx = half ? Bq.y : Aq.z;
            float avy = half ? Bq.z : Aq.w;
            float avz = half ? Bq.w : Bq.x;
            unsigned long long as2  = pack2(as, as);
            unsigned long long avx2 = pack2(avx, avx);
            unsigned long long avy2 = pack2(avy, avy);
            unsigned long long avz2 = pack2(avz, avz);
            fma2(accs2[0], as2, ws.x);
            fma2(accs2[1], as2, ws.y);
            fma2(accv2[0][0], avx2, wv.x);
            fma2(accv2[0][1], avx2, wv.y);
            fma2(accv2[1][0], avy2, wv.x);
            fma2(accv2[1][1], avy2, wv.y);
            fma2(accv2[2][0], avz2, wv.x);
            fma2(accv2[2][1], avz2, wv.y);
        }
    }

    unsigned long long at2[8];
    const float* arow = attrs + node * 8;
#pragma unroll
    for (int v = 0; v < 8; v++) { float a = arow[v]; at2[v] = pack2(a, a); }

    const float* srow = node_s + node * 32;
    const float* vrow = node_v + node * 96;
#pragma unroll 2
    for (int u = 0; u < 32; u++) {
        float su = srow[u];
        float vx = vrow[u * 3 + 0], vy = vrow[u * 3 + 1], vz = vrow[u * 3 + 2];
        unsigned long long Ts[2] = {0ull, 0ull};
        unsigned long long Tv[2] = {0ull, 0ull};
#pragma unroll
        for (int v = 0; v < 8; v++) {
            ulonglong2 ps = *(const ulonglong2*)&sWscs[(u * 8 + v) * 32 + wo];
            ulonglong2 pv = *(const ulonglong2*)&sWscv[(u * 8 + v) * 32 + wo];
            fma2(Ts[0], at2[v], ps.x);
            fma2(Ts[1], at2[v], ps.y);
            fma2(Tv[0], at2[v], pv.x);
            fma2(Tv[1], at2[v], pv.y);
        }
        unsigned long long su2 = pack2(su, su);
        unsigned long long vx2 = pack2(vx, vx);
        unsigned long long vy2 = pack2(vy, vy);
        unsigned long long vz2 = pack2(vz, vz);
#pragma unroll
        for (int p = 0; p < 2; p++) {
            fma2(accs2[p], su2, Ts[p]);
            fma2(accv2[0][p], vx2, Tv[p]);
            fma2(accv2[1][p], vy2, Tv[p]);
            fma2(accv2[2][p], vz2, Tv[p]);
        }
    }

    float* o = out + (size_t)node * 128;
#pragma unroll
    for (int p = 0; p < 2; p++) {
        float s0, s1;
        unpack2(s0, s1, accs2[p]);
        float v0[3], v1[3];
        unpack2(v0[0], v1[0], accv2[0][p]);
        unpack2(v0[1], v1[1], accv2[1][p]);
        unpack2(v0[2], v1[2], accv2[2][p]);
        int w0 = wo + p * 2;
        o[w0]     = s0;
        o[w0 + 1] = s1;
        o[32 + w0 * 3 + 0] = v0[0];
        o[32 + w0 * 3 + 1] = v0[1];
        o[32 + w0 * 3 + 2] = v0[2];
        o[32 + (w0 + 1) * 3 + 0] = v1[0];
        o[32 + (w0 + 1) * 3 + 1] = v1[1];
        o[32 + (w0 + 1) * 3 + 2] = v1[2];
    }
}

// ---------------------------------------------------------------------------
extern "C" void kernel_launch(void* const* d_in, const int* in_sizes, int n_in,
                              void* d_out, int out_size) {
    const float* node_s     = (const float*)d_in[0];
    const float* node_v     = (const float*)d_in[1];
    const float* node_attrs = (const float*)d_in[2];
    const float* edge_emb   = (const float*)d_in[3];
    const float* edge_y0    = (const float*)d_in[4];
    const float* edge_y1    = (const float*)d_in[5];
    const int*   edge_index = (const int*)d_in[6];
    const float* W1s        = (const float*)d_in[7];
    const float* W1v        = (const float*)d_in[8];
    const float* Wr1        = (const float*)d_in[9];
    const float* Wr2        = (const float*)d_in[10];
    const float* W2s        = (const float*)d_in[11];
    const float* W2v        = (const float*)d_in[12];
    const float* Wscs       = (const float*)d_in[13];
    const float* Wscv       = (const float*)d_in[14];
    float* out = (float*)d_out;

    cudaFuncSetAttribute(k_edge, cudaFuncAttributeMaxDynamicSharedMemorySize,
                         EDGE_SMEM_FLOATS * sizeof(float));
    cudaFuncSetAttribute(k_out, cudaFuncAttributeMaxDynamicSharedMemorySize,
                         OUT_SMEM_FLOATS * sizeof(float));

    k_zero<<<5000, 256>>>();
    k_hist<<<2500, 256>>>(edge_index);
    k_scan<<<1, 1024>>>();
    k_scatter<<<2500, 256>>>(edge_index);
    k_lin1<<<(2 * N_NODES + 255) / 256, 256>>>(node_s, node_v, W1s, W1v);
    k_edge<<<N_EDGES / ET, 256, EDGE_SMEM_FLOATS * sizeof(float)>>>(
        edge_emb, edge_y0, edge_y1, edge_index, Wr1, Wr2);
    k_out<<<(N_NODES * 8) / 256, 256, OUT_SMEM_FLOATS * sizeof(float)>>>(
        node_s, node_v, node_attrs, W2s, W2v, Wscs, Wscv, out);
}

// round 8
// speedup vs baseline: 1.1091x; 1.0502x over previous
#include <cuda_runtime.h>
#include <cstdint>

#define N_NODES 20000
#define N_EDGES 640000
#define MUL 32
#define ATTR 8
#define RB 16
#define FH 64

#define INV_M      0.17677669529663687f
#define INV_RB     0.25f
#define INV_FH     0.125f
#define INV_SQRT3  0.5773502691896258f
#define INV_DEG    0.17677669529663687f
#define INV_2M     0.125f
#define INV_FAN    0.0625f
#define LOG2F_     0.6931471805599453f

// Scratch (device globals)
__device__ float g_s[N_NODES * MUL];
__device__ float g_v[N_NODES * MUL * 3];      // SoA: [node][comp(3)][u(32)]
__device__ float g_agg[N_NODES * MUL * 8];
// sort scratch
__device__ int g_cnt[N_NODES];
__device__ int g_pos[N_NODES];
__device__ int g_off[N_NODES + 1];
__device__ int g_perm[N_EDGES];

__device__ __forceinline__ float sspf(float x) {
    return fmaxf(x, 0.0f) + log1pf(__expf(-fabsf(x))) - LOG2F_;
}

// no "memory" clobber — g_agg is write-only here and atomic adds commute
__device__ __forceinline__ void red_add_v4(float* addr, float a, float b, float c, float d) {
    asm volatile("red.global.add.v4.f32 [%0], {%1,%2,%3,%4};"
                 :: "l"(addr), "f"(a), "f"(b), "f"(c), "f"(d));
}

// ---- packed f32x2 helpers ----
__device__ __forceinline__ unsigned long long pack2(float x, float y) {
    unsigned long long r;
    asm("mov.b64 %0, {%1,%2};" : "=l"(r) : "f"(x), "f"(y));
    return r;
}
__device__ __forceinline__ void unpack2(float& x, float& y, unsigned long long r) {
    asm("mov.b64 {%0,%1}, %2;" : "=f"(x), "=f"(y) : "l"(r));
}
__device__ __forceinline__ void fma2(unsigned long long& d, unsigned long long a,
                                     unsigned long long b) {
    asm("fma.rn.f32x2 %0, %1, %2, %0;" : "+l"(d) : "l"(a), "l"(b));
}

// ---- bf16 pack helpers ----
__device__ __forceinline__ unsigned bf16x2_of(float x1, float x0) {
    unsigned r;
    asm("cvt.rn.bf16x2.f32 %0, %1, %2;" : "=r"(r) : "f"(x1), "f"(x0));
    return r;
}
__device__ __forceinline__ void bf16_hilo(float x0, float x1, unsigned& hi, unsigned& lo) {
    hi = bf16x2_of(x1, x0);
    float h0 = __uint_as_float(hi << 16);
    float h1 = __uint_as_float(hi & 0xffff0000u);
    lo = bf16x2_of(x1 - h1, x0 - h0);
}

__device__ __forceinline__ void mma16816(float* d, const unsigned* a, const unsigned* b) {
    asm volatile(
        "mma.sync.aligned.m16n8k16.row.col.f32.bf16.bf16.f32 "
        "{%0,%1,%2,%3}, {%4,%5,%6,%7}, {%8,%9}, {%0,%1,%2,%3};"
        : "+f"(d[0]), "+f"(d[1]), "+f"(d[2]), "+f"(d[3])
        : "r"(a[0]), "r"(a[1]), "r"(a[2]), "r"(a[3]), "r"(b[0]), "r"(b[1]));
}

// ---------------------------------------------------------------------------
__global__ void k_zero() {
    int i = blockIdx.x * blockDim.x + threadIdx.x;
    float4* p = reinterpret_cast<float4*>(g_agg);
    p[i] = make_float4(0.f, 0.f, 0.f, 0.f);
    if (i < N_NODES) { g_cnt[i] = 0; g_pos[i] = 0; }
}

__global__ void k_hist(const int* __restrict__ eidx) {
    int e = blockIdx.x * blockDim.x + threadIdx.x;
    if (e < N_EDGES) atomicAdd(&g_cnt[eidx[N_EDGES + e]], 1);
}

__global__ void k_scan() {
    __shared__ int sh[1024];
    int tid = threadIdx.x;
    int base = tid * 20;
    int loc[20];
    int s = 0;
#pragma unroll
    for (int j = 0; j < 20; j++) {
        int idx = base + j;
        int c = (idx < N_NODES) ? g_cnt[idx] : 0;
        loc[j] = s;
        s += c;
    }
    sh[tid] = s;
    __syncthreads();
    for (int off = 1; off < 1024; off <<= 1) {
        int v = (tid >= off) ? sh[tid - off] : 0;
        __syncthreads();
        sh[tid] += v;
        __syncthreads();
    }
    int pre = (tid == 0) ? 0 : sh[tid - 1];
#pragma unroll
    for (int j = 0; j < 20; j++) {
        int idx = base + j;
        if (idx < N_NODES) g_off[idx] = pre + loc[j];
    }
    if (tid == 1023) g_off[N_NODES] = sh[1023];
}

__global__ void k_scatter(const int* __restrict__ eidx) {
    int e = blockIdx.x * blockDim.x + threadIdx.x;
    if (e < N_EDGES) {
        int dst = eidx[N_EDGES + e];
        int r = atomicAdd(&g_pos[dst], 1);
        g_perm[g_off[dst] + r] = e;
    }
}

// ---------------------------------------------------------------------------
// Kernel 1: linear_1 (writes g_v in SoA [node][comp][32])
// ---------------------------------------------------------------------------
__global__ void k_lin1(const float* __restrict__ node_s,
                       const float* __restrict__ node_v,
                       const float* __restrict__ W1s,
                       const float* __restrict__ W1v) {
    __shared__ float sW1s[1024];
    __shared__ float sW1v[1024];
    int tid = threadIdx.x;
    for (int i = tid; i < 1024; i += 256) {
        sW1s[i] = W1s[i] * INV_M;
        sW1v[i] = W1v[i] * INV_M;
    }
    __syncthreads();

    int gt = blockIdx.x * 256 + tid;
    int node = gt >> 1;
    int h = gt & 1;
    if (node >= N_NODES) return;

    float accs[16];
    float accv[16][3];
#pragma unroll
    for (int w = 0; w < 16; w++) { accs[w] = 0.f; accv[w][0] = accv[w][1] = accv[w][2] = 0.f; }

    const float* srow = node_s + node * 32;
    const float* vrow = node_v + node * 96;
    for (int u = 0; u < 32; u++) {
        float su = srow[u];
        float vx = vrow[u * 3 + 0], vy = vrow[u * 3 + 1], vz = vrow[u * 3 + 2];
        const float* ws = &sW1s[u * 32 + h * 16];
        const float* wv = &sW1v[u * 32 + h * 16];
#pragma unroll
        for (int w = 0; w < 16; w++) {
            accs[w]    += su * ws[w];
            accv[w][0] += vx * wv[w];
            accv[w][1] += vy * wv[w];
            accv[w][2] += vz * wv[w];
        }
    }
    float* so = g_s + node * 32 + h * 16;
    float* vo = g_v + node * 96 + h * 16;     // SoA: + comp*32
#pragma unroll
    for (int w = 0; w < 16; w++) {
        so[w] = accs[w];
        vo[w]      = accv[w][0];
        vo[32 + w] = accv[w][1];
        vo[64 + w] = accv[w][2];
    }
}

// ---------------------------------------------------------------------------
// Kernel 2: edge kernel, 512 threads (16 warps) for latency hiding.
// GEMM1 scalar fp32; GEMM2 via mma.sync bf16 hi/lo 3-term split;
// warp-cooperative TP (8 edges/warp) with pipelined coalesced gathers.
// ---------------------------------------------------------------------------
#define ET 128
#define ETHREADS 512
#define PHA_HI 0
#define PHA_LO 4224
#define PB_HI  8448
#define PB_LO  12672
#define WR1_OFF 16896
#define EMB_OFF 17920
#define META_OFF 20096
#define EDGE_SMEM_FLOATS 20992

__global__ void __launch_bounds__(ETHREADS, 2)
k_edge(const float* __restrict__ emb,
       const float* __restrict__ y0,
       const float* __restrict__ y1,
       const int*   __restrict__ eidx,
       const float* __restrict__ Wr1,
       const float* __restrict__ Wr2) {
    extern __shared__ float sm[];
    unsigned* su   = reinterpret_cast<unsigned*>(sm);
    float* sw   = sm;                     // overlay after MMA
    float* sWr1 = sm + WR1_OFF;
    float* semb = sm + EMB_OFF;
    int*   sperm = (int*)(sm + META_OFF);
    int*   ssrc  = sperm + 128;
    int*   sdst  = ssrc + 128;
    float* sy0   = (float*)(sdst + 128);
    float* sy1   = sy0 + 128;

    int tid = threadIdx.x;
    int p0 = blockIdx.x * ET;

    if (tid < 128) sperm[tid] = g_perm[p0 + tid];
    for (int i = tid; i < 1024; i += ETHREADS) sWr1[i] = Wr1[i] * INV_RB;
    for (int i = tid; i < 4096; i += ETHREADS) {
        int n = i & 127, kk = i >> 7;
        float sc = INV_FH * INV_DEG * ((n >= 96) ? INV_SQRT3 : 1.0f);
        float w0 = Wr2[(2 * kk) * 128 + n] * sc;
        float w1 = Wr2[(2 * kk + 1) * 128 + n] * sc;
        unsigned hi, lo;
        bf16_hilo(w0, w1, hi, lo);
        su[PB_HI + n * 33 + kk] = hi;
        su[PB_LO + n * 33 + kk] = lo;
    }
    __syncthreads();

    if (tid < 128) {
        int e = sperm[tid];
        ssrc[tid] = eidx[e];
        sdst[tid] = eidx[N_EDGES + e];
        sy0[tid] = y0[e];
    }
    for (int i = tid; i < 384; i += ETHREADS) {
        int pos = i / 3, comp = i - pos * 3;
        sy1[i] = y1[sperm[pos] * 3 + comp];
    }
    for (int i = tid; i < ET * RB; i += ETHREADS) {
        int pos = i >> 4, k = i & 15;
        semb[pos * 17 + k] = emb[sperm[pos] * 16 + k];
    }
    __syncthreads();

    int lane = tid & 31;
    int th = tid >> 5;          // 0..15
    int cg = th >> 1;           // GEMM1 col group 0..7
    int eh = th & 1;            // GEMM1 edge half

    // ---- GEMM1 (fp32): 2 edges x 8 cols per thread ----
    float acc1[2][8];
#pragma unroll
    for (int j = 0; j < 2; j++)
#pragma unroll
        for (int m = 0; m < 8; m++) acc1[j][m] = 0.f;

    for (int k = 0; k < 16; k++) {
        float em[2];
#pragma unroll
        for (int j = 0; j < 2; j++) em[j] = semb[(lane + 32 * (eh * 2 + j)) * 17 + k];
        float wr[8];
#pragma unroll
        for (int m = 0; m < 8; m++) wr[m] = sWr1[k * 64 + cg * 8 + m];
#pragma unroll
        for (int j = 0; j < 2; j++)
#pragma unroll
            for (int m = 0; m < 8; m++) acc1[j][m] += em[j] * wr[m];
    }
#pragma unroll
    for (int j = 0; j < 2; j++) {
        int edge = lane + 32 * (eh * 2 + j);
#pragma unroll
        for (int m = 0; m < 8; m += 2) {
            float x0 = sspf(acc1[j][m]);
            float x1 = sspf(acc1[j][m + 1]);
            unsigned hi, lo;
            bf16_hilo(x0, x1, hi, lo);
            int kk = cg * 4 + (m >> 1);
            su[PHA_HI + edge * 33 + kk] = hi;
            su[PHA_LO + edge * 33 + kk] = lo;
        }
    }
    __syncthreads();

    // ---- GEMM2 via mma.sync: warp pair (mt, nh) ----
    int g = lane >> 2;
    int t = lane & 3;
    int mt = th >> 1;           // M-tile: edges [mt*16, mt*16+16)
    int nh = th & 1;            // N half: nt in [nh*8, nh*8+8)
    float d[8][4];
#pragma unroll
    for (int ntl = 0; ntl < 8; ntl++)
#pragma unroll
        for (int c = 0; c < 4; c++) d[ntl][c] = 0.f;

    {
        int r0 = mt * 16 + g;
        int r1 = r0 + 8;
#pragma unroll
        for (int ks = 0; ks < 4; ks++) {
            int kk0 = ks * 8 + t;
            unsigned ahi[4], alo[4];
            ahi[0] = su[PHA_HI + r0 * 33 + kk0];
            ahi[1] = su[PHA_HI + r1 * 33 + kk0];
            ahi[2] = su[PHA_HI + r0 * 33 + kk0 + 4];
            ahi[3] = su[PHA_HI + r1 * 33 + kk0 + 4];
            alo[0] = su[PHA_LO + r0 * 33 + kk0];
            alo[1] = su[PHA_LO + r1 * 33 + kk0];
            alo[2] = su[PHA_LO + r0 * 33 + kk0 + 4];
            alo[3] = su[PHA_LO + r1 * 33 + kk0 + 4];
#pragma unroll
            for (int ntl = 0; ntl < 8; ntl++) {
                int n = (nh * 8 + ntl) * 8 + g;
                unsigned bhi[2], blo[2];
                bhi[0] = su[PB_HI + n * 33 + kk0];
                bhi[1] = su[PB_HI + n * 33 + kk0 + 4];
                blo[0] = su[PB_LO + n * 33 + kk0];
                blo[1] = su[PB_LO + n * 33 + kk0 + 4];
                mma16816(d[ntl], ahi, bhi);
                mma16816(d[ntl], alo, bhi);
                mma16816(d[ntl], ahi, blo);
            }
        }
    }
    __syncthreads();   // phA/pB dead; safe to overlay sw

    // ---- store D -> sw[edge][col] with xor swizzle ----
    {
        int e0 = mt * 16 + g;
        int e1 = e0 + 8;
        int sw0 = (e0 & 7) << 2;
        int sw1 = (e1 & 7) << 2;
#pragma unroll
        for (int ntl = 0; ntl < 8; ntl++) {
            int c = (nh * 8 + ntl) * 8 + 2 * t;
            int b = c & ~31;
            int cc = c & 31;
            *(float2*)&sw[e0 * 128 + b + (cc ^ sw0)] = make_float2(d[ntl][0], d[ntl][1]);
            *(float2*)&sw[e1 * 128 + b + (cc ^ sw1)] = make_float2(d[ntl][2], d[ntl][3]);
        }
    }
    __syncthreads();   // TP warp reads rows produced by its warp pair

    // ---- warp-cooperative TP: warp th owns edges [th*8, th*8+8), lane = u ----
    int base = th * 8;

    float se_r[8];
#pragma unroll
    for (int j = 0; j < 8; j++) se_r[j] = g_s[ssrc[base + j] * 32 + lane];

    const float* vp0 = g_v + ssrc[base] * 96 + lane;
    float vxc = vp0[0], vyc = vp0[32], vzc = vp0[64];

    float A[8];
#pragma unroll
    for (int q = 0; q < 8; q++) A[q] = 0.f;

    int cur = sdst[base];
#pragma unroll
    for (int j = 0; j < 8; j++) {
        int pos = base + j;
        float vxn = 0.f, vyn = 0.f, vzn = 0.f;
        if (j < 7) {
            const float* vpn = g_v + ssrc[pos + 1] * 96 + lane;
            vxn = vpn[0]; vyn = vpn[32]; vzn = vpn[64];
        }
        int dd = sdst[pos];
        if (dd != cur) {
            float* q = g_agg + (size_t)cur * 256 + lane * 8;
            red_add_v4(q,     A[0], A[1], A[2], A[3]);
            red_add_v4(q + 4, A[4], A[5], A[6], A[7]);
#pragma unroll
            for (int qq = 0; qq < 8; qq++) A[qq] = 0.f;
            cur = dd;
        }
        float yy0 = sy0[pos];
        float y1x = sy1[pos * 3 + 0], y1y = sy1[pos * 3 + 1], y1z = sy1[pos * 3 + 2];
        float se = se_r[j];
        int sx = lane ^ ((pos & 7) << 2);
        int wb = pos * 128;
        float w1 = sw[wb + sx], w2 = sw[wb + 32 + sx], w3 = sw[wb + 64 + sx], w4 = sw[wb + 96 + sx];

        A[0] += w1 * (se * yy0);
        A[1] += w4 * (vxc * y1x + vyc * y1y + vzc * y1z);
        float a = w2 * se;
        A[2] += a * y1x; A[3] += a * y1y; A[4] += a * y1z;
        float b = w3 * yy0;
        A[5] += b * vxc; A[6] += b * vyc; A[7] += b * vzc;

        vxc = vxn; vyc = vyn; vzc = vzn;
    }
    float* q = g_agg + (size_t)cur * 256 + lane * 8;
    red_add_v4(q,     A[0], A[1], A[2], A[3]);
    red_add_v4(q + 4, A[4], A[5], A[6], A[7]);
}

// ---------------------------------------------------------------------------
// Kernel 3: linear_2 + self-connection
// ---------------------------------------------------------------------------
#define OUT_SMEM_FLOATS (2048 + 2048 + 8192 + 8192)

__global__ void __launch_bounds__(256)
k_out(const float* __restrict__ node_s,
      const float* __restrict__ node_v,
      const float* __restrict__ attrs,
      const float* __restrict__ W2s,
      const float* __restrict__ W2v,
      const float* __restrict__ Wscs,
      const float* __restrict__ Wscv,
      float* __restrict__ out) {
    extern __shared__ float sm[];
    float* sW2s  = sm;
    float* sW2v  = sW2s + 2048;
    float* sWscs = sW2v + 2048;
    float* sWscv = sWscs + 8192;

    int tid = threadIdx.x;
    for (int i = tid; i < 2048; i += 256) { sW2s[i]  = W2s[i]  * INV_2M;  sW2v[i]  = W2v[i]  * INV_2M; }
    for (int i = tid; i < 8192; i += 256) { sWscs[i] = Wscs[i] * INV_FAN; sWscv[i] = Wscv[i] * INV_FAN; }
    __syncthreads();

    int node = blockIdx.x * 32 + (tid >> 3);
    int part = tid & 7;
    int wo = part * 4;

    unsigned long long accs2[2] = {0ull, 0ull};
    unsigned long long accv2[3][2] = {{0ull, 0ull}, {0ull, 0ull}, {0ull, 0ull}};

    const float4* ag = reinterpret_cast<const float4*>(g_agg + (size_t)node * 256);
#pragma unroll 4
    for (int u = 0; u < 32; u++) {
        float4 Aq = ag[u * 2 + 0];
        float4 Bq = ag[u * 2 + 1];
#pragma unroll
        for (int half = 0; half < 2; half++) {
            int k = half * 32 + u;
            ulonglong2 ws = *(const ulonglong2*)&sW2s[k * 32 + wo];
            ulonglong2 wv = *(const ulonglong2*)&sW2v[k * 32 + wo];
            float as  = half ? Aq.y : Aq.x;
            float avx = half ? Bq.y : Aq.z;
            float avy = half ? Bq.z : Aq.w;
            float avz = half ? Bq.w : Bq.x;
            unsigned long long as2  = pack2(as, as);
            unsigned long long avx2 = pack2(avx, avx);
            unsigned long long avy2 = pack2(avy, avy);
            unsigned long long avz2 = pack2(avz, avz);
            fma2(accs2[0], as2, ws.x);
            fma2(accs2[1], as2, ws.y);
            fma2(accv2[0][0], avx2, wv.x);
            fma2(accv2[0][1], avx2, wv.y);
            fma2(accv2[1][0], avy2, wv.x);
            fma2(accv2[1][1], avy2, wv.y);
            fma2(accv2[2][0], avz2, wv.x);
            fma2(accv2[2][1], avz2, wv.y);
        }
    }

    unsigned long long at2[8];
    const float* arow = attrs + node * 8;
#pragma unroll
    for (int v = 0; v < 8; v++) { float a = arow[v]; at2[v] = pack2(a, a); }

    const float* srow = node_s + node * 32;
    const float* vrow = node_v + node * 96;
#pragma unroll 2
    for (int u = 0; u < 32; u++) {
        float su = srow[u];
        float vx = vrow[u * 3 + 0], vy = vrow[u * 3 + 1], vz = vrow[u * 3 + 2];
        unsigned long long Ts[2] = {0ull, 0ull};
        unsigned long long Tv[2] = {0ull, 0ull};
#pragma unroll
        for (int v = 0; v < 8; v++) {
            ulonglong2 ps = *(const ulonglong2*)&sWscs[(u * 8 + v) * 32 + wo];
            ulonglong2 pv = *(const ulonglong2*)&sWscv[(u * 8 + v) * 32 + wo];
            fma2(Ts[0], at2[v], ps.x);
            fma2(Ts[1], at2[v], ps.y);
            fma2(Tv[0], at2[v], pv.x);
            fma2(Tv[1], at2[v], pv.y);
        }
        unsigned long long su2 = pack2(su, su);
        unsigned long long vx2 = pack2(vx, vx);
        unsigned long long vy2 = pack2(vy, vy);
        unsigned long long vz2 = pack2(vz, vz);
#pragma unroll
        for (int p = 0; p < 2; p++) {
            fma2(accs2[p], su2, Ts[p]);
            fma2(accv2[0][p], vx2, Tv[p]);
            fma2(accv2[1][p], vy2, Tv[p]);
            fma2(accv2[2][p], vz2, Tv[p]);
        }
    }

    float* o = out + (size_t)node * 128;
#pragma unroll
    for (int p = 0; p < 2; p++) {
        float s0, s1;
        unpack2(s0, s1, accs2[p]);
        float v0[3], v1[3];
        unpack2(v0[0], v1[0], accv2[0][p]);
        unpack2(v0[1], v1[1], accv2[1][p]);
        unpack2(v0[2], v1[2], accv2[2][p]);
        int w0 = wo + p * 2;
        o[w0]     = s0;
        o[w0 + 1] = s1;
        o[32 + w0 * 3 + 0] = v0[0];
        o[32 + w0 * 3 + 1] = v0[1];
        o[32 + w0 * 3 + 2] = v0[2];
        o[32 + (w0 + 1) * 3 + 0] = v1[0];
        o[32 + (w0 + 1) * 3 + 1] = v1[1];
        o[32 + (w0 + 1) * 3 + 2] = v1[2];
    }
}

// ---------------------------------------------------------------------------
extern "C" void kernel_launch(void* const* d_in, const int* in_sizes, int n_in,
                              void* d_out, int out_size) {
    const float* node_s     = (const float*)d_in[0];
    const float* node_v     = (const float*)d_in[1];
    const float* node_attrs = (const float*)d_in[2];
    const float* edge_emb   = (const float*)d_in[3];
    const float* edge_y0    = (const float*)d_in[4];
    const float* edge_y1    = (const float*)d_in[5];
    const int*   edge_index = (const int*)d_in[6];
    const float* W1s        = (const float*)d_in[7];
    const float* W1v        = (const float*)d_in[8];
    const float* Wr1        = (const float*)d_in[9];
    const float* Wr2        = (const float*)d_in[10];
    const float* W2s        = (const float*)d_in[11];
    const float* W2v        = (const float*)d_in[12];
    const float* Wscs       = (const float*)d_in[13];
    const float* Wscv       = (const float*)d_in[14];
    float* out = (float*)d_out;

    cudaFuncSetAttribute(k_edge, cudaFuncAttributeMaxDynamicSharedMemorySize,
                         EDGE_SMEM_FLOATS * sizeof(float));
    cudaFuncSetAttribute(k_out, cudaFuncAttributeMaxDynamicSharedMemorySize,
                         OUT_SMEM_FLOATS * sizeof(float));

    k_zero<<<5000, 256>>>();
    k_hist<<<2500, 256>>>(edge_index);
    k_scan<<<1, 1024>>>();
    k_scatter<<<2500, 256>>>(edge_index);
    k_lin1<<<(2 * N_NODES + 255) / 256, 256>>>(node_s, node_v, W1s, W1v);
    k_edge<<<N_EDGES / ET, ETHREADS, EDGE_SMEM_FLOATS * sizeof(float)>>>(
        edge_emb, edge_y0, edge_y1, edge_index, Wr1, Wr2);
    k_out<<<(N_NODES * 8) / 256, 256, OUT_SMEM_FLOATS * sizeof(float)>>>(
        node_s, node_v, node_attrs, W2s, W2v, Wscs, Wscv, out);
}